// round 1
// baseline (speedup 1.0000x reference)
#include <cuda_runtime.h>

// Problem constants
#define IMG_W   512
#define OH      113          // (512-64)/4 + 1
#define NWIN    (OH*OH)      // 12769 windows
#define PITCH   128          // stride-4 grid dimension (512/4)

// Scratch pyramids: level L holds max/min of (4<<L)x(4<<L) blocks whose origin
// is at stride-4 grid position (i,j) (pixel (4i,4j)). Pitch 128 at every level.
__device__ float g_mx[5][PITCH*PITCH];
__device__ float g_mn[5][PITCH*PITCH];

// ---------------------------------------------------------------------------
// Level 0: 4x4 block max/min over all 128x128 stride-4 origins.
// Each thread handles one origin; rows loaded as float4 (perfectly coalesced
// across consecutive threads since columns are 16B-aligned and consecutive).
// ---------------------------------------------------------------------------
__global__ void k_level0(const float* __restrict__ img) {
    int t = blockIdx.x * blockDim.x + threadIdx.x;
    if (t >= PITCH * PITCH) return;
    int r = t >> 7;         // origin row / 4
    int c = t & 127;        // origin col / 4  (== float4 column index)
    const float4* p4 = (const float4*)img;
    float mx = -3.4e38f, mn = 3.4e38f;
#pragma unroll
    for (int k = 0; k < 4; k++) {
        float4 v = p4[(4 * r + k) * (IMG_W / 4) + c];
        mx = fmaxf(mx, fmaxf(fmaxf(v.x, v.y), fmaxf(v.z, v.w)));
        mn = fminf(mn, fminf(fminf(v.x, v.y), fminf(v.z, v.w)));
    }
    g_mx[0][t] = mx;
    g_mn[0][t] = mn;
}

// ---------------------------------------------------------------------------
// Hierarchy: level L (size 2s) from level L-1 (size s).
//   out(i,j) = combine of src at (i,j),(i+d,j),(i,j+d),(i+d,j+d),  d = s/4.
// n = number of valid indices per dim at level L (n = 128 - (1<<L) ... derived).
// ---------------------------------------------------------------------------
__global__ void k_build(int L, int d, int n) {
    int t = blockIdx.x * blockDim.x + threadIdx.x;
    if (t >= n * n) return;
    int i = t / n, j = t - i * n;
    const float* __restrict__ sx = g_mx[L - 1];
    const float* __restrict__ sn = g_mn[L - 1];
    int b = i * PITCH + j;
    float mx = fmaxf(fmaxf(sx[b], sx[b + d]),
                     fmaxf(sx[b + d * PITCH], sx[b + d * PITCH + d]));
    float mn = fminf(fminf(sn[b], sn[b + d]),
                     fminf(sn[b + d * PITCH], sn[b + d * PITCH + d]));
    g_mx[L][b] = mx;
    g_mn[L][b] = mn;
}

// ---------------------------------------------------------------------------
// Per-window fractal dimension. One warp per window.
// Window (I,J): boxes at scale level L live at grid index
//   (I + p*(1<<L), J + q*(1<<L)),  p,q in [0, 16>>L).
// Box counts per level: 256, 64, 16, 4, 1  -> lanes split them.
// slope = sum(ln s_L * ln d_b_L) / sum(ln s_L ^2);  ln s_L = (L+2) ln2
//   => fd = -sum((L+2) * ln d_b_L) / (ln2 * 90)
// ---------------------------------------------------------------------------
__global__ void k_fd(float* __restrict__ out) {
    int gwarp = (blockIdx.x * blockDim.x + threadIdx.x) >> 5;
    int lane  = threadIdx.x & 31;
    if (gwarp >= NWIN) return;
    int I = gwarp / OH;
    int J = gwarp - I * OH;
    int base = I * PITCH + J;

    float s0 = 0.f, s1 = 0.f, s2 = 0.f, s3 = 0.f, s4 = 0.f;

    // L0: 256 boxes, 8 per lane
#pragma unroll
    for (int b = 0; b < 8; b++) {
        int blk = lane + b * 32;
        int idx = base + (blk >> 4) * PITCH + (blk & 15);
        s0 += g_mx[0][idx] - g_mn[0][idx];
    }
    // L1: 64 boxes, 2 per lane
#pragma unroll
    for (int b = 0; b < 2; b++) {
        int blk = lane + b * 32;
        int idx = base + ((blk >> 3) * 2) * PITCH + (blk & 7) * 2;
        s1 += g_mx[1][idx] - g_mn[1][idx];
    }
    // L2: 16 boxes
    if (lane < 16) {
        int idx = base + ((lane >> 2) * 4) * PITCH + (lane & 3) * 4;
        s2 = g_mx[2][idx] - g_mn[2][idx];
    }
    // L3: 4 boxes
    if (lane < 4) {
        int idx = base + ((lane >> 1) * 8) * PITCH + (lane & 1) * 8;
        s3 = g_mx[3][idx] - g_mn[3][idx];
    }
    // L4: 1 box
    if (lane == 0) s4 = g_mx[4][base] - g_mn[4][base];

    // Butterfly reductions (s4 needs none, it's only on lane 0)
#pragma unroll
    for (int off = 16; off > 0; off >>= 1) {
        s0 += __shfl_xor_sync(0xFFFFFFFFu, s0, off);
        s1 += __shfl_xor_sync(0xFFFFFFFFu, s1, off);
        s2 += __shfl_xor_sync(0xFFFFFFFFu, s2, off);
        s3 += __shfl_xor_sync(0xFFFFFFFFu, s3, off);
    }

    if (lane == 0) {
        const float INV_LN2_90 = 1.0f / (0.69314718055994531f * 90.0f);
        float num = 2.0f * logf(s0) + 3.0f * logf(s1) + 4.0f * logf(s2)
                  + 5.0f * logf(s3) + 6.0f * logf(s4);
        out[gwarp] = -num * INV_LN2_90;
    }
}

// ---------------------------------------------------------------------------
extern "C" void kernel_launch(void* const* d_in, const int* in_sizes, int n_in,
                              void* d_out, int out_size) {
    const float* img = (const float*)d_in[0];
    float* out = (float*)d_out;

    // Level 0: 128x128 origins
    k_level0<<<(PITCH * PITCH + 255) / 256, 256>>>(img);

    // Hierarchical levels: (L, d, n)
    //   L1 (s=8):  d=1, n=127
    //   L2 (s=16): d=2, n=125
    //   L3 (s=32): d=4, n=121
    //   L4 (s=64): d=8, n=113
    k_build<<<(127 * 127 + 255) / 256, 256>>>(1, 1, 127);
    k_build<<<(125 * 125 + 255) / 256, 256>>>(2, 2, 125);
    k_build<<<(121 * 121 + 255) / 256, 256>>>(3, 4, 121);
    k_build<<<(113 * 113 + 255) / 256, 256>>>(4, 8, 113);

    // FD regression: one warp per window, 8 warps per block
    k_fd<<<(NWIN + 7) / 8, 256>>>(out);
}

// round 3
// speedup vs baseline: 1.9329x; 1.9329x over previous
#include <cuda_runtime.h>

#define OH   113          // output windows per dim
#define P    33           // smem row pitch (bank-conflict-free)

// Stacked row offsets for the 5 pyramid levels inside one smem array.
// Local rows needed per level for a 16x16 window tile:
//   L0: 16+15=31, L1: 16+14=30, L2: 16+12=28, L3: 16+8=24, L4: 16
#define R0   0
#define R1   (31*P)
#define R2   (R1 + 30*P)
#define R3   (R2 + 28*P)
#define R4   (R3 + 24*P)
#define RT   (R4 + 16*P)   // 129*33 = 4257 words

__global__ __launch_bounds__(256)
void k_fused(const float* __restrict__ img, float* __restrict__ out) {
    __shared__ float smx[RT];        // max pyramid, later holds ranges
    __shared__ float smn[RT];        // min pyramid
    __shared__ float c0[31 * 16];    // L0 column sums (16 taps)
    __shared__ float c1[30 * 16];    // L1 column sums (8 taps, stride 2)

    const int tid = threadIdx.x;
    const int I0 = blockIdx.y * 16;  // tile origin in stride-4 grid units
    const int J0 = blockIdx.x * 16;

    // ---- Phase A: level-0 4x4 max/min over 31x31 local stride-4 origins ----
    const float4* p4 = (const float4*)img;
    for (int e = tid; e < 31 * 31; e += 256) {
        int i = e / 31, j = e - i * 31;
        int gi = I0 + i, gj = J0 + j;
        if (gi < 128 && gj < 128) {           // guard global loads only
            float mx = -3.4e38f, mn = 3.4e38f;
#pragma unroll
            for (int k = 0; k < 4; k++) {
                float4 v = p4[(4 * gi + k) * 128 + gj];
                mx = fmaxf(mx, fmaxf(fmaxf(v.x, v.y), fmaxf(v.z, v.w)));
                mn = fminf(mn, fminf(fminf(v.x, v.y), fminf(v.z, v.w)));
            }
            smx[R0 + i * P + j] = mx;
            smn[R0 + i * P + j] = mn;
        }
    }
    __syncthreads();

    // ---- Phase B: hierarchical levels (all in smem) ----
    // (src, dst, n_local, d): out(i,j) = combine src (i,j),(i+d,j),(i,j+d),(i+d,j+d)
    {
        const int srcs[4] = {R0, R1, R2, R3};
        const int dsts[4] = {R1, R2, R3, R4};
        const int ns[4]   = {30, 28, 24, 16};
        const int ds[4]   = {1, 2, 4, 8};
#pragma unroll 1
        for (int L = 0; L < 4; L++) {
            int src = srcs[L], dst = dsts[L], n = ns[L], d = ds[L];
            for (int e = tid; e < n * n; e += 256) {
                int i = e / n, j = e - i * n;
                int b = src + i * P + j;
                float mx = fmaxf(fmaxf(smx[b], smx[b + d]),
                                 fmaxf(smx[b + d * P], smx[b + d * P + d]));
                float mn = fminf(fminf(smn[b], smn[b + d]),
                                 fminf(smn[b + d * P], smn[b + d * P + d]));
                smx[dst + i * P + j] = mx;
                smn[dst + i * P + j] = mn;
            }
            __syncthreads();
        }
    }

    // ---- Phase C: collapse to ranges in place (smx <- smx - smn) ----
    for (int e = tid; e < RT; e += 256) smx[e] = smx[e] - smn[e];
    __syncthreads();

    // ---- Phase D: separable column sums for L0 and L1 ----
    for (int e = tid; e < 31 * 16; e += 256) {
        int i = e >> 4, J = e & 15;
        float s = 0.f;
#pragma unroll
        for (int q = 0; q < 16; q++) s += smx[R0 + i * P + J + q];
        c0[e] = s;
    }
    for (int e = tid; e < 30 * 16; e += 256) {
        int i = e >> 4, J = e & 15;
        float s = 0.f;
#pragma unroll
        for (int q = 0; q < 8; q++) s += smx[R1 + i * P + J + 2 * q];
        c1[e] = s;
    }
    __syncthreads();

    // ---- Phase E: one thread per window ----
    int ti = tid >> 4, tj = tid & 15;
    float s0 = 0.f, s1 = 0.f, s2 = 0.f, s3 = 0.f;
#pragma unroll
    for (int p = 0; p < 16; p++) s0 += c0[(ti + p) * 16 + tj];
#pragma unroll
    for (int p = 0; p < 8; p++)  s1 += c1[(ti + 2 * p) * 16 + tj];
#pragma unroll
    for (int p = 0; p < 4; p++)
#pragma unroll
        for (int q = 0; q < 4; q++)
            s2 += smx[R2 + (ti + 4 * p) * P + tj + 4 * q];
#pragma unroll
    for (int p = 0; p < 2; p++)
#pragma unroll
        for (int q = 0; q < 2; q++)
            s3 += smx[R3 + (ti + 8 * p) * P + tj + 8 * q];
    float s4 = smx[R4 + ti * P + tj];

    int I = I0 + ti, Jw = J0 + tj;
    if (I < OH && Jw < OH) {
        const float INV_LN2_90 = 1.0f / (0.69314718055994531f * 90.0f);
        float num = 2.0f * logf(s0) + 3.0f * logf(s1) + 4.0f * logf(s2)
                  + 5.0f * logf(s3) + 6.0f * logf(s4);
        out[I * OH + Jw] = -num * INV_LN2_90;
    }
}

// ---------------------------------------------------------------------------
extern "C" void kernel_launch(void* const* d_in, const int* in_sizes, int n_in,
                              void* d_out, int out_size) {
    const float* img = (const float*)d_in[0];
    float* out = (float*)d_out;
    dim3 grid(8, 8);           // ceil(113/16) per dim
    k_fused<<<grid, 256>>>(img, out);
}

// round 4
// speedup vs baseline: 2.4375x; 1.2610x over previous
#include <cuda_runtime.h>

#define OH   113        // output windows per dim
#define P    24         // smem row pitch for pyramid levels

// Tile: 16 windows in I, 8 in J. Local pyramid extents (rows x cols):
//   L0: 31x23  L1: 30x22  L2: 28x20  L3: 24x16  L4: 16x8
#define R0   0
#define R1   (31*P)              // 744
#define R2   (R1 + 30*P)         // 1464
#define R3   (R2 + 28*P)         // 2136
#define R4   (R3 + 24*P)         // 2712
#define RT   (R4 + 16*P)         // 3096 words

__global__ __launch_bounds__(256)
void k_fused(const float* __restrict__ img, float* __restrict__ out) {
    __shared__ float smx[RT];       // max pyramid
    __shared__ float smn[RT];       // min pyramid
    __shared__ float c0[31 * 9];    // L0 column range-sums (16 taps), pitch 9
    __shared__ float c1[30 * 9];    // L1 column range-sums (8 taps, stride 2)

    const int tid = threadIdx.x;
    const int I0 = blockIdx.y * 16;     // tile origin, stride-4 grid units
    const int J0 = blockIdx.x * 8;

    // ---- Phase A: level-0 4x4 max/min over 31x23 local origins ----
    const float4* p4 = (const float4*)img;
    for (int e = tid; e < 31 * 23; e += 256) {
        int i = e / 23, j = e - i * 23;
        int gi = I0 + i, gj = J0 + j;
        if (gi < 128 && gj < 128) {     // guard global loads only
            float mx = -3.4e38f, mn = 3.4e38f;
#pragma unroll
            for (int k = 0; k < 4; k++) {
                float4 v = p4[(4 * gi + k) * 128 + gj];
                mx = fmaxf(mx, fmaxf(fmaxf(v.x, v.y), fmaxf(v.z, v.w)));
                mn = fminf(mn, fminf(fminf(v.x, v.y), fminf(v.z, v.w)));
            }
            smx[R0 + i * P + j] = mx;
            smn[R0 + i * P + j] = mn;
        }
    }
    __syncthreads();

    // ---- Phase B: hierarchical levels (fully unrolled constant offsets) ----
#define BUILD(SRC, DST, NR, NC, D)                                          \
    for (int e = tid; e < (NR) * (NC); e += 256) {                          \
        int i = e / (NC), j = e - i * (NC);                                 \
        int b = (SRC) + i * P + j;                                          \
        smx[(DST) + i * P + j] =                                            \
            fmaxf(fmaxf(smx[b], smx[b + (D)]),                              \
                  fmaxf(smx[b + (D) * P], smx[b + (D) * P + (D)]));         \
        smn[(DST) + i * P + j] =                                            \
            fminf(fminf(smn[b], smn[b + (D)]),                              \
                  fminf(smn[b + (D) * P], smn[b + (D) * P + (D)]));         \
    }                                                                       \
    __syncthreads();

    BUILD(R0, R1, 30, 22, 1)
    BUILD(R1, R2, 28, 20, 2)
    BUILD(R2, R3, 24, 16, 4)
    BUILD(R3, R4, 16,  8, 8)
#undef BUILD

    // ---- Phase D: separable column sums of ranges for L0 and L1 ----
    for (int e = tid; e < 31 * 8; e += 256) {
        int i = e >> 3, J = e & 7;
        float s = 0.f;
#pragma unroll
        for (int q = 0; q < 16; q++) {
            int a = R0 + i * P + J + q;
            s += smx[a] - smn[a];
        }
        c0[i * 9 + J] = s;
    }
    for (int e = tid; e < 30 * 8; e += 256) {
        int i = e >> 3, J = e & 7;
        float s = 0.f;
#pragma unroll
        for (int q = 0; q < 8; q++) {
            int a = R1 + i * P + J + 2 * q;
            s += smx[a] - smn[a];
        }
        c1[i * 9 + J] = s;
    }
    __syncthreads();

    // ---- Phase E: 2 threads per window, taps split by parity ----
    int w  = tid >> 1;          // window 0..127
    int h  = tid & 1;           // tap half
    int ti = w >> 3, tj = w & 7;

    float s0 = 0.f, s1 = 0.f, s2 = 0.f, s3 = 0.f, s4 = 0.f;
#pragma unroll
    for (int k = 0; k < 8; k++)                 // s0: rows p = h*8+k
        s0 += c0[(ti + h * 8 + k) * 9 + tj];
#pragma unroll
    for (int k = 0; k < 4; k++)                 // s1: rows p = h*4+k
        s1 += c1[(ti + 2 * (h * 4 + k)) * 9 + tj];
#pragma unroll
    for (int pp = 0; pp < 2; pp++)              // s2: p = h*2+pp, q 0..3
#pragma unroll
        for (int q = 0; q < 4; q++) {
            int a = R2 + (ti + 4 * (h * 2 + pp)) * P + tj + 4 * q;
            s2 += smx[a] - smn[a];
        }
#pragma unroll
    for (int q = 0; q < 2; q++) {               // s3: p = h, q 0..1
        int a = R3 + (ti + 8 * h) * P + tj + 8 * q;
        s3 += smx[a] - smn[a];
    }
    if (h == 0) {
        int a = R4 + ti * P + tj;
        s4 = smx[a] - smn[a];
    }

    s0 += __shfl_xor_sync(0xFFFFFFFFu, s0, 1);
    s1 += __shfl_xor_sync(0xFFFFFFFFu, s1, 1);
    s2 += __shfl_xor_sync(0xFFFFFFFFu, s2, 1);
    s3 += __shfl_xor_sync(0xFFFFFFFFu, s3, 1);

    int I = I0 + ti, J = J0 + tj;
    if (h == 0 && I < OH && J < OH) {
        float num = 2.0f * __log2f(s0) + 3.0f * __log2f(s1)
                  + 4.0f * __log2f(s2) + 5.0f * __log2f(s3)
                  + 6.0f * __log2f(s4);
        out[I * OH + J] = -num * (1.0f / 90.0f);
    }
}

// ---------------------------------------------------------------------------
extern "C" void kernel_launch(void* const* d_in, const int* in_sizes, int n_in,
                              void* d_out, int out_size) {
    const float* img = (const float*)d_in[0];
    float* out = (float*)d_out;
    dim3 grid(15, 8);           // 15 J-tiles x 8 I-tiles = 120 CTAs (~1 wave)
    k_fused<<<grid, 256>>>(img, out);
}

// round 5
// speedup vs baseline: 2.4465x; 1.0037x over previous
#include <cuda_runtime.h>

#define OH   113        // output windows per dim
#define P    25         // smem row pitch for pyramid levels

// Tile: 8x8 windows. Local pyramid extents (rows x cols):
//   L0: 23x23  L1: 22x22  L2: 20x20   (L3/L4 computed on the fly in epilogue)
#define R0   0
#define R1   (23*P)              // 575
#define R2   (R1 + 22*P)         // 1125
#define RT   (R2 + 20*P)         // 1625 words (~6.5KB per array)

__global__ __launch_bounds__(256)
void k_fused(const float* __restrict__ img, float* __restrict__ out) {
    __shared__ float smx[RT];       // max pyramid
    __shared__ float smn[RT];       // min pyramid
    __shared__ float c0[23 * 9];    // L0 column range-sums (16 taps), pitch 9
    __shared__ float c1[22 * 9];    // L1 column range-sums (8 taps, stride 2)

    const int tid = threadIdx.x;
    const int I0 = blockIdx.y * 8;      // tile origin, stride-4 grid units
    const int J0 = blockIdx.x * 8;

    // ---- Phase A: level-0 4x4 max/min over 23x23 local origins ----
    const float4* p4 = (const float4*)img;
    for (int e = tid; e < 23 * 23; e += 256) {
        int i = e / 23, j = e - i * 23;
        int gi = I0 + i, gj = J0 + j;
        if (gi < 128 && gj < 128) {     // guard global loads only
            float mx = -3.4e38f, mn = 3.4e38f;
#pragma unroll
            for (int k = 0; k < 4; k++) {
                float4 v = p4[(4 * gi + k) * 128 + gj];
                mx = fmaxf(mx, fmaxf(fmaxf(v.x, v.y), fmaxf(v.z, v.w)));
                mn = fminf(mn, fminf(fminf(v.x, v.y), fminf(v.z, v.w)));
            }
            smx[R0 + i * P + j] = mx;
            smn[R0 + i * P + j] = mn;
        }
    }
    __syncthreads();

    // ---- Phase 1: build L1 (22x22) and c0 (23x8, 16 taps) — both from L0 ----
    for (int e = tid; e < 22 * 22 + 23 * 8; e += 256) {
        if (e < 22 * 22) {
            int i = e / 22, j = e - i * 22;
            int b = R0 + i * P + j;
            smx[R1 + i * P + j] = fmaxf(fmaxf(smx[b], smx[b + 1]),
                                        fmaxf(smx[b + P], smx[b + P + 1]));
            smn[R1 + i * P + j] = fminf(fminf(smn[b], smn[b + 1]),
                                        fminf(smn[b + P], smn[b + P + 1]));
        } else {
            int f = e - 22 * 22;
            int i = f >> 3, J = f & 7;
            float s = 0.f;
#pragma unroll
            for (int q = 0; q < 16; q++) {
                int a = R0 + i * P + J + q;
                s += smx[a] - smn[a];
            }
            c0[i * 9 + J] = s;
        }
    }
    __syncthreads();

    // ---- Phase 2: build L2 (20x20) and c1 (22x8, 8 taps) — both from L1 ----
    for (int e = tid; e < 20 * 20 + 22 * 8; e += 256) {
        if (e < 20 * 20) {
            int i = e / 20, j = e - i * 20;
            int b = R1 + i * P + j;
            smx[R2 + i * P + j] = fmaxf(fmaxf(smx[b], smx[b + 2]),
                                        fmaxf(smx[b + 2 * P], smx[b + 2 * P + 2]));
            smn[R2 + i * P + j] = fminf(fminf(smn[b], smn[b + 2]),
                                        fminf(smn[b + 2 * P], smn[b + 2 * P + 2]));
        } else {
            int f = e - 20 * 20;
            int i = f >> 3, J = f & 7;
            float s = 0.f;
#pragma unroll
            for (int q = 0; q < 8; q++) {
                int a = R1 + i * P + J + 2 * q;
                s += smx[a] - smn[a];
            }
            c1[i * 9 + J] = s;
        }
    }
    __syncthreads();

    // ---- Phase E: 4 threads per window ----
    int w  = tid >> 2;          // window 0..63
    int h  = tid & 3;           // quarter index
    int ti = w >> 3, tj = w & 7;

    float s0 = 0.f, s1 = 0.f, s2 = 0.f, s3;
    // s0: 16 c0 rows, 4 per thread
#pragma unroll
    for (int k = 0; k < 4; k++)
        s0 += c0[(ti + h * 4 + k) * 9 + tj];
    // s1: 8 c1 rows (stride 2), 2 per thread
#pragma unroll
    for (int k = 0; k < 2; k++)
        s1 += c1[(ti + 2 * (h * 2 + k)) * 9 + tj];
    // s2: 16 L2 ranges, thread h takes row p=h
#pragma unroll
    for (int q = 0; q < 4; q++) {
        int a = R2 + (ti + 4 * h) * P + tj + 4 * q;
        s2 += smx[a] - smn[a];
    }
    // s3: 4 boxes of 32x32; thread h owns box (p,q)=(h>>1,h&1): max/min of 4 L2
    {
        int bp = h >> 1, bq = h & 1;
        int b = R2 + (ti + 8 * bp) * P + tj + 8 * bq;
        float mx = fmaxf(fmaxf(smx[b], smx[b + 4]),
                         fmaxf(smx[b + 4 * P], smx[b + 4 * P + 4]));
        float mn = fminf(fminf(smn[b], smn[b + 4]),
                         fminf(smn[b + 4 * P], smn[b + 4 * P + 4]));
        s3 = mx - mn;
    }
    // s4: 64x64 box = max/min over 16 L2 entries; thread h takes row a=h
    float mx4 = -3.4e38f, mn4 = 3.4e38f;
#pragma unroll
    for (int q = 0; q < 4; q++) {
        int a = R2 + (ti + 4 * h) * P + tj + 4 * q;
        mx4 = fmaxf(mx4, smx[a]);
        mn4 = fminf(mn4, smn[a]);
    }

    // Reduce across the 4-thread group (consecutive lanes in a warp)
#pragma unroll
    for (int off = 1; off <= 2; off <<= 1) {
        s0  += __shfl_xor_sync(0xFFFFFFFFu, s0, off);
        s1  += __shfl_xor_sync(0xFFFFFFFFu, s1, off);
        s2  += __shfl_xor_sync(0xFFFFFFFFu, s2, off);
        s3  += __shfl_xor_sync(0xFFFFFFFFu, s3, off);
        mx4 = fmaxf(mx4, __shfl_xor_sync(0xFFFFFFFFu, mx4, off));
        mn4 = fminf(mn4, __shfl_xor_sync(0xFFFFFFFFu, mn4, off));
    }

    int I = I0 + ti, J = J0 + tj;
    if (h == 0 && I < OH && J < OH) {
        float s4 = mx4 - mn4;
        float num = 2.0f * __log2f(s0) + 3.0f * __log2f(s1)
                  + 4.0f * __log2f(s2) + 5.0f * __log2f(s3)
                  + 6.0f * __log2f(s4);
        out[I * OH + J] = -num * (1.0f / 90.0f);
    }
}

// ---------------------------------------------------------------------------
extern "C" void kernel_launch(void* const* d_in, const int* in_sizes, int n_in,
                              void* d_out, int out_size) {
    const float* img = (const float*)d_in[0];
    float* out = (float*)d_out;
    dim3 grid(15, 15);          // ceil(113/8) per dim = 225 CTAs
    k_fused<<<grid, 256>>>(img, out);
}